// round 10
// baseline (speedup 1.0000x reference)
#include <cuda_runtime.h>
#include <cuda_fp16.h>
#include <mma.h>

using namespace nvcuda;

#define N_NODES 50000
#define FEAT 128
#define E_MAX 1600000

// ---------------- scratch (static device globals; no allocation) ----------------
__device__ __align__(16) __half g_h16a[(size_t)N_NODES * FEAT];   // layer-1 GEMM output (gather payload)
__device__ __align__(16) __half g_h16b[(size_t)N_NODES * FEAT];   // layer-2 GEMM output (gather payload)
__device__ float g_rs_out[N_NODES];
__device__ float g_rs_in[N_NODES];
__device__ int   g_deg_out[N_NODES];
__device__ int   g_deg_in[N_NODES];
__device__ int   g_offsets[N_NODES + 1];
__device__ int   g_cursor[N_NODES];
__device__ int   g_csr_src[E_MAX];
__device__ int   g_blocksums[64];

// ---------------- degree kernels ----------------
__global__ void init_deg_kernel(int* deg_out, int* deg_in, int n) {
    int i = blockIdx.x * blockDim.x + threadIdx.x;
    if (i < n) { deg_out[i] = 0; deg_in[i] = 0; }
}

// 4 edges per thread via int4; tail handled by block 0.
__global__ void count_deg_kernel(const int* __restrict__ src, const int* __restrict__ dst,
                                 int* deg_out, int* deg_in, int e) {
    int i = blockIdx.x * blockDim.x + threadIdx.x;
    int e4 = e >> 2;
    if (i < e4) {
        int4 s = __ldg((const int4*)src + i);
        int4 d = __ldg((const int4*)dst + i);
        atomicAdd(&deg_out[s.x], 1); atomicAdd(&deg_out[s.y], 1);
        atomicAdd(&deg_out[s.z], 1); atomicAdd(&deg_out[s.w], 1);
        atomicAdd(&deg_in[d.x], 1);  atomicAdd(&deg_in[d.y], 1);
        atomicAdd(&deg_in[d.z], 1);  atomicAdd(&deg_in[d.w], 1);
    }
    if (blockIdx.x == 0 && threadIdx.x < (e & 3)) {
        int t = e4 * 4 + threadIdx.x;
        atomicAdd(&deg_out[src[t]], 1);
        atomicAdd(&deg_in[dst[t]], 1);
    }
}

// ---------------- parallel exclusive scan (3 phases) + rs finalize ----------------
__global__ void scan_block_kernel(const int* __restrict__ deg_in, const int* __restrict__ deg_out,
                                  int* __restrict__ excl, int* __restrict__ blocksums,
                                  float* __restrict__ rs_out, float* __restrict__ rs_in, int n) {
    int i = blockIdx.x * 1024 + threadIdx.x;
    int v = (i < n) ? deg_in[i] : 0;
    if (i < n) {
        rs_in[i]  = rsqrtf((float)max(v, 1));
        rs_out[i] = rsqrtf((float)max(deg_out[i], 1));
    }
    int lane = threadIdx.x & 31, w = threadIdx.x >> 5;
    int x = v;
    #pragma unroll
    for (int o = 1; o < 32; o <<= 1) {
        int y = __shfl_up_sync(0xffffffffu, x, o);
        if (lane >= o) x += y;
    }
    __shared__ int wt[32];
    if (lane == 31) wt[w] = x;
    __syncthreads();
    if (w == 0) {
        int t = wt[lane];
        #pragma unroll
        for (int o = 1; o < 32; o <<= 1) {
            int y = __shfl_up_sync(0xffffffffu, t, o);
            if (lane >= o) t += y;
        }
        wt[lane] = t;
    }
    __syncthreads();
    int base = (w > 0) ? wt[w - 1] : 0;
    int incl = base + x;
    if (i < n) excl[i] = incl - v;
    if (threadIdx.x == 1023) blocksums[blockIdx.x] = incl;
}

__global__ void scan_sums_kernel(int* bs, int nb) {
    int tid = threadIdx.x;              // 64 threads, nb <= 64
    int v = (tid < nb) ? bs[tid] : 0;
    int lane = tid & 31, w = tid >> 5;
    int x = v;
    #pragma unroll
    for (int o = 1; o < 32; o <<= 1) {
        int y = __shfl_up_sync(0xffffffffu, x, o);
        if (lane >= o) x += y;
    }
    __shared__ int wt[2];
    if (lane == 31) wt[w] = x;
    __syncthreads();
    int base = (w == 1) ? wt[0] : 0;
    int incl = base + x;
    if (tid < nb) bs[tid] = incl - v;   // exclusive
}

__global__ void scan_add_kernel(int* __restrict__ offsets, const int* __restrict__ bs,
                                int* __restrict__ cursor, int n, int e) {
    int i = blockIdx.x * 1024 + threadIdx.x;
    if (i < n) {
        int o = offsets[i] + bs[blockIdx.x];
        offsets[i] = o;
        cursor[i] = o;
    }
    if (blockIdx.x == 0 && threadIdx.x == 0) offsets[n] = e;
}

// 4 edges per thread via int4; tail handled by block 0.
__global__ void csr_fill_kernel(const int* __restrict__ src, const int* __restrict__ dst,
                                int* cursor, int* __restrict__ csr_src, int e) {
    int i = blockIdx.x * blockDim.x + threadIdx.x;
    int e4 = e >> 2;
    if (i < e4) {
        int4 s = __ldg((const int4*)src + i);
        int4 d = __ldg((const int4*)dst + i);
        int p0 = atomicAdd(&cursor[d.x], 1);
        int p1 = atomicAdd(&cursor[d.y], 1);
        int p2 = atomicAdd(&cursor[d.z], 1);
        int p3 = atomicAdd(&cursor[d.w], 1);
        csr_src[p0] = s.x; csr_src[p1] = s.y;
        csr_src[p2] = s.z; csr_src[p3] = s.w;
    }
    if (blockIdx.x == 0 && threadIdx.x < (e & 3)) {
        int t = e4 * 4 + threadIdx.x;
        int pos = atomicAdd(&cursor[dst[t]], 1);
        csr_src[pos] = src[t];
    }
}

// ---------------- shared wmma compute + epilogue ----------------
template <int N_OUT, int HALF_OUT>
__device__ __forceinline__ void wmma_compute_store(
    __half* Ws, __half* Xs, float* Ys, void* Yv, int row0, int rows, int tid,
    const float* post_bias) {
    constexpr int K = 128;
    constexpr int LDW = N_OUT + 8;
    constexpr int LDX = K + 8;
    constexpr int LDY = N_OUT + 4;
    constexpr int NF = (N_OUT / 2) / 16;

    int warp = tid >> 5;
    int warp_m = warp >> 1;
    int warp_n = warp & 1;

    wmma::fragment<wmma::accumulator, 16, 16, 16, float> acc[NF];
    #pragma unroll
    for (int j = 0; j < NF; j++) wmma::fill_fragment(acc[j], 0.0f);

    wmma::fragment<wmma::matrix_a, 16, 16, 16, __half, wmma::row_major> a_frag;
    wmma::fragment<wmma::matrix_b, 16, 16, 16, __half, wmma::row_major> b_frag;

    #pragma unroll
    for (int k = 0; k < K / 16; k++) {
        wmma::load_matrix_sync(a_frag, Xs + (warp_m * 16) * LDX + k * 16, LDX);
        #pragma unroll
        for (int j = 0; j < NF; j++) {
            wmma::load_matrix_sync(b_frag, Ws + (k * 16) * LDW + warp_n * (N_OUT / 2) + j * 16, LDW);
            wmma::mma_sync(acc[j], a_frag, b_frag, acc[j]);
        }
    }
    __syncthreads();   // smem reads done before Ys aliases Ws/Xs

    #pragma unroll
    for (int j = 0; j < NF; j++) {
        wmma::store_matrix_sync(Ys + (warp_m * 16) * LDY + warp_n * (N_OUT / 2) + j * 16,
                                acc[j], LDY, wmma::mem_row_major);
    }
    __syncthreads();

    for (int i = tid; i < rows * (N_OUT / 4); i += 256) {
        int r = i / (N_OUT / 4);
        int c = (i % (N_OUT / 4)) * 4;
        float4 o = *(float4*)(Ys + r * LDY + c);
        if (post_bias) {
            o.x += post_bias[c + 0];
            o.y += post_bias[c + 1];
            o.z += post_bias[c + 2];
            o.w += post_bias[c + 3];
        }
        if (HALF_OUT) {
            __half* Yh = (__half*)Yv;
            __half2 p0 = __floats2half2_rn(o.x, o.y);
            __half2 p1 = __floats2half2_rn(o.z, o.w);
            uint2 st; st.x = *(unsigned int*)&p0; st.y = *(unsigned int*)&p1;
            *(uint2*)(Yh + (size_t)(row0 + r) * N_OUT + c) = st;
        } else {
            *(float4*)((float*)Yv + (size_t)(row0 + r) * N_OUT + c) = o;
        }
    }
}

// ---------------- layer-1 GEMM: h16a = (x * rs_out) @ W1 ----------------
__global__ void gemm1_kernel(const float* __restrict__ X, const float* __restrict__ W,
                             __half* __restrict__ Y, int n_rows,
                             const float* __restrict__ rs_a) {
    constexpr int K = 128, N_OUT = 128, TILE_M = 64;
    constexpr int LDW = N_OUT + 8, LDX = K + 8;

    extern __shared__ char smem_raw[];
    __half* Ws = (__half*)smem_raw;
    __half* Xs = (__half*)(smem_raw + K * LDW * 2);
    float*  Ys = (float*)smem_raw;

    int tid = threadIdx.x;
    int row0 = blockIdx.x * TILE_M;
    int rows = min(TILE_M, n_rows - row0);

    const float4* W4 = (const float4*)W;
    for (int i = tid; i < K * (N_OUT / 4); i += 256) {
        int k = i / (N_OUT / 4);
        int c = (i % (N_OUT / 4)) * 4;
        float4 v = W4[i];
        __half2 p0 = __floats2half2_rn(v.x, v.y);
        __half2 p1 = __floats2half2_rn(v.z, v.w);
        uint2 st; st.x = *(unsigned int*)&p0; st.y = *(unsigned int*)&p1;
        *(uint2*)(Ws + k * LDW + c) = st;
    }

    if (rows < TILE_M) {
        int n_half = (TILE_M - rows) * LDX;
        __half* base = Xs + rows * LDX;
        for (int i = tid; i < n_half; i += 256) base[i] = __ushort_as_half(0);
    }

    const float4* X4 = (const float4*)(X + (size_t)row0 * K);
    for (int i = tid; i < rows * (K / 4); i += 256) {
        float4 v = X4[i];
        int r = i / (K / 4);
        int c = (i % (K / 4)) * 4;
        float sa = rs_a[row0 + r];
        v.x *= sa; v.y *= sa; v.z *= sa; v.w *= sa;
        __half2 p0 = __floats2half2_rn(v.x, v.y);
        __half2 p1 = __floats2half2_rn(v.z, v.w);
        uint2 st; st.x = *(unsigned int*)&p0; st.y = *(unsigned int*)&p1;
        *(uint2*)(Xs + r * LDX + c) = st;
    }
    __syncthreads();

    wmma_compute_store<128, 1>(Ws, Xs, Ys, Y, row0, rows, tid, nullptr);
}

// ---------------- fused aggregate + GEMM ----------------
// For each dst row r:  m = sum_{s in N(r)} feat16[s]        (fp32 accum, fp16 payload)
// PRE==2: x = relu(m * rs_in[r] + pre_bias) * rs_out[r]      (layer 2, fp16 out)
// PRE==3: x = m * rs_in[r] + pre_bias                        (final, fp32 out + post_bias)
// Y = x @ W (+ post_bias)
template <int N_OUT, int PRE, int HALF_OUT>
__global__ void agg_gemm_kernel(const __half* __restrict__ feat, const float* __restrict__ W,
                                void* __restrict__ Yv, int n_rows,
                                const int* __restrict__ offsets, const int* __restrict__ csr_src,
                                const float* __restrict__ rs_in, const float* __restrict__ rs_out,
                                const float* __restrict__ pre_bias,
                                const float* __restrict__ post_bias) {
    constexpr int K = 128, TILE_M = 64;
    constexpr int LDW = N_OUT + 8, LDX = K + 8;

    extern __shared__ char smem_raw[];
    __half* Ws = (__half*)smem_raw;
    __half* Xs = (__half*)(smem_raw + K * LDW * 2);
    float*  Ys = (float*)smem_raw;

    int tid = threadIdx.x;
    int warp = tid >> 5;
    int lane = tid & 31;
    int row0 = blockIdx.x * TILE_M;
    int rows = min(TILE_M, n_rows - row0);

    // load W -> fp16 smem
    const float4* W4 = (const float4*)W;
    for (int i = tid; i < K * (N_OUT / 4); i += 256) {
        int k = i / (N_OUT / 4);
        int c = (i % (N_OUT / 4)) * 4;
        float4 v = W4[i];
        __half2 p0 = __floats2half2_rn(v.x, v.y);
        __half2 p1 = __floats2half2_rn(v.z, v.w);
        uint2 st; st.x = *(unsigned int*)&p0; st.y = *(unsigned int*)&p1;
        *(uint2*)(Ws + k * LDW + c) = st;
    }

    // gather + pre-op into Xs: warp handles 8 rows, lane covers features lane*4..lane*4+3
    const uint2* base = (const uint2*)feat;
    float bx = 0.f, by = 0.f, bz = 0.f, bw = 0.f;
    {
        int c = lane * 4;
        bx = pre_bias[c + 0]; by = pre_bias[c + 1];
        bz = pre_bias[c + 2]; bw = pre_bias[c + 3];
    }

    #pragma unroll 1
    for (int rr = 0; rr < 8; rr++) {
        int row = row0 + warp * 8 + rr;
        float4 a0 = make_float4(0.f, 0.f, 0.f, 0.f);
        float4 a1 = make_float4(0.f, 0.f, 0.f, 0.f);
        float4 a2 = make_float4(0.f, 0.f, 0.f, 0.f);
        float4 a3 = make_float4(0.f, 0.f, 0.f, 0.f);
        if (row < n_rows) {
            int beg = __ldg(offsets + row);
            int end = __ldg(offsets + row + 1);
            int k = beg;
            for (; k + 4 <= end; k += 4) {
                int s0 = __ldg(csr_src + k + 0);
                int s1 = __ldg(csr_src + k + 1);
                int s2 = __ldg(csr_src + k + 2);
                int s3 = __ldg(csr_src + k + 3);
                uint2 v0 = __ldg(base + (size_t)s0 * 32 + lane);
                uint2 v1 = __ldg(base + (size_t)s1 * 32 + lane);
                uint2 v2 = __ldg(base + (size_t)s2 * 32 + lane);
                uint2 v3 = __ldg(base + (size_t)s3 * 32 + lane);
                {
                    __half2 h0 = *(__half2*)&v0.x; __half2 h1 = *(__half2*)&v0.y;
                    float2 f0 = __half22float2(h0); float2 f1 = __half22float2(h1);
                    a0.x += f0.x; a0.y += f0.y; a0.z += f1.x; a0.w += f1.y;
                }
                {
                    __half2 h0 = *(__half2*)&v1.x; __half2 h1 = *(__half2*)&v1.y;
                    float2 f0 = __half22float2(h0); float2 f1 = __half22float2(h1);
                    a1.x += f0.x; a1.y += f0.y; a1.z += f1.x; a1.w += f1.y;
                }
                {
                    __half2 h0 = *(__half2*)&v2.x; __half2 h1 = *(__half2*)&v2.y;
                    float2 f0 = __half22float2(h0); float2 f1 = __half22float2(h1);
                    a2.x += f0.x; a2.y += f0.y; a2.z += f1.x; a2.w += f1.y;
                }
                {
                    __half2 h0 = *(__half2*)&v3.x; __half2 h1 = *(__half2*)&v3.y;
                    float2 f0 = __half22float2(h0); float2 f1 = __half22float2(h1);
                    a3.x += f0.x; a3.y += f0.y; a3.z += f1.x; a3.w += f1.y;
                }
            }
            for (; k < end; k++) {
                int s = __ldg(csr_src + k);
                uint2 v = __ldg(base + (size_t)s * 32 + lane);
                __half2 h0 = *(__half2*)&v.x; __half2 h1 = *(__half2*)&v.y;
                float2 f0 = __half22float2(h0); float2 f1 = __half22float2(h1);
                a0.x += f0.x; a0.y += f0.y; a0.z += f1.x; a0.w += f1.y;
            }
        }
        a0.x += a1.x + a2.x + a3.x;
        a0.y += a1.y + a2.y + a3.y;
        a0.z += a1.z + a2.z + a3.z;
        a0.w += a1.w + a2.w + a3.w;

        // pre-op
        float si = (row < n_rows) ? rs_in[row] : 0.f;
        a0.x = a0.x * si + bx;
        a0.y = a0.y * si + by;
        a0.z = a0.z * si + bz;
        a0.w = a0.w * si + bw;
        if (PRE == 2) {
            float so = (row < n_rows) ? rs_out[row] : 0.f;
            a0.x = fmaxf(a0.x, 0.f) * so;
            a0.y = fmaxf(a0.y, 0.f) * so;
            a0.z = fmaxf(a0.z, 0.f) * so;
            a0.w = fmaxf(a0.w, 0.f) * so;
        }
        if (row >= n_rows) { a0.x = 0.f; a0.y = 0.f; a0.z = 0.f; a0.w = 0.f; }

        __half2 p0 = __floats2half2_rn(a0.x, a0.y);
        __half2 p1 = __floats2half2_rn(a0.z, a0.w);
        uint2 st; st.x = *(unsigned int*)&p0; st.y = *(unsigned int*)&p1;
        *(uint2*)(Xs + (warp * 8 + rr) * LDX + lane * 4) = st;
    }
    __syncthreads();

    wmma_compute_store<N_OUT, HALF_OUT>(Ws, Xs, Ys, Yv, row0, rows, tid, post_bias);
}

// ---------------- launch ----------------
extern "C" void kernel_launch(void* const* d_in, const int* in_sizes, int n_in,
                              void* d_out, int out_size) {
    const float* in_feat = (const float*)d_in[0];
    const int*   src     = (const int*)d_in[1];
    const int*   dst     = (const int*)d_in[2];
    const float* W1      = (const float*)d_in[3];
    const float* b1      = (const float*)d_in[4];
    const float* W2      = (const float*)d_in[5];
    const float* b2      = (const float*)d_in[6];
    const float* Wf      = (const float*)d_in[7];
    const float* bf      = (const float*)d_in[8];
    float* out = (float*)d_out;

    int n = in_sizes[0] / FEAT;   // 50000
    int e = in_sizes[1];          // 1600000

    float *rs_out, *rs_in;
    __half *h16a, *h16b;
    int *dgo, *dgi, *offs, *curs, *csrc, *bsum;
    cudaGetSymbolAddress((void**)&h16a, g_h16a);
    cudaGetSymbolAddress((void**)&h16b, g_h16b);
    cudaGetSymbolAddress((void**)&rs_out, g_rs_out);
    cudaGetSymbolAddress((void**)&rs_in, g_rs_in);
    cudaGetSymbolAddress((void**)&dgo, g_deg_out);
    cudaGetSymbolAddress((void**)&dgi, g_deg_in);
    cudaGetSymbolAddress((void**)&offs, g_offsets);
    cudaGetSymbolAddress((void**)&curs, g_cursor);
    cudaGetSymbolAddress((void**)&csrc, g_csr_src);
    cudaGetSymbolAddress((void**)&bsum, g_blocksums);

    const int SMEM_128 = 128 * 136 * 2 + 64 * 136 * 2;  // 52224 (Ys 64*132*4=33792 aliases)
    const int SMEM_64  = 128 * 72 * 2 + 64 * 136 * 2;   // 35840
    cudaFuncSetAttribute(gemm1_kernel, cudaFuncAttributeMaxDynamicSharedMemorySize, SMEM_128);
    cudaFuncSetAttribute(agg_gemm_kernel<128, 2, 1>, cudaFuncAttributeMaxDynamicSharedMemorySize, SMEM_128);
    cudaFuncSetAttribute(agg_gemm_kernel<64, 3, 0>,  cudaFuncAttributeMaxDynamicSharedMemorySize, SMEM_64);

    // degrees + CSR (graph identical for both layers; build once)
    init_deg_kernel<<<(n + 255) / 256, 256>>>(dgo, dgi, n);
    int e4 = e >> 2;
    count_deg_kernel<<<(e4 + 255) / 256, 256>>>(src, dst, dgo, dgi, e);

    int nscan_blocks = (n + 1023) / 1024;   // 49
    scan_block_kernel<<<nscan_blocks, 1024>>>(dgi, dgo, offs, bsum, rs_out, rs_in, n);
    scan_sums_kernel<<<1, 64>>>(bsum, nscan_blocks);
    scan_add_kernel<<<nscan_blocks, 1024>>>(offs, bsum, curs, n, e);
    csr_fill_kernel<<<(e4 + 255) / 256, 256>>>(src, dst, curs, csrc, e);

    int gemm_blocks = (n + 63) / 64;

    // layer 1: h16a = (x * rs_out) @ W1
    gemm1_kernel<<<gemm_blocks, 256, SMEM_128>>>(in_feat, W1, h16a, n, rs_out);

    // layer 2 (fused): h16b = (relu(agg(h16a) * rs_in + b1) * rs_out) @ W2
    agg_gemm_kernel<128, 2, 1><<<gemm_blocks, 256, SMEM_128>>>(
        h16a, W2, h16b, n, offs, csrc, rs_in, rs_out, b1, nullptr);

    // final (fused): out = (agg(h16b) * rs_in + b2) @ Wf + bf
    agg_gemm_kernel<64, 3, 0><<<gemm_blocks, 256, SMEM_64>>>(
        h16b, Wf, out, n, offs, csrc, rs_in, rs_out, b2, bf);
}

// round 14
// speedup vs baseline: 1.1506x; 1.1506x over previous
#include <cuda_runtime.h>
#include <cuda_fp16.h>
#include <mma.h>

using namespace nvcuda;

#define N_NODES 50000
#define FEAT 128
#define E_MAX 1600000

// ---------------- scratch (static device globals; no allocation) ----------------
__device__ __align__(16) float  g_buf0[(size_t)N_NODES * FEAT];   // fp32 aggregation output
__device__ __align__(16) __half g_h16[(size_t)N_NODES * FEAT];    // fp16 GEMM output (gather payload)
__device__ float g_rs_out[N_NODES];
__device__ float g_rs_in[N_NODES];
__device__ int   g_deg_out[N_NODES];
__device__ int   g_deg_in[N_NODES];
__device__ int   g_offsets[N_NODES + 1];
__device__ int   g_cursor[N_NODES];
__device__ int   g_csr_src[E_MAX];
__device__ int   g_blocksums[64];

// ---------------- degree kernels ----------------
__global__ void init_deg_kernel(int* deg_out, int* deg_in, int n) {
    int i = blockIdx.x * blockDim.x + threadIdx.x;
    if (i < n) { deg_out[i] = 0; deg_in[i] = 0; }
}

// 4 edges per thread via int4; tail handled by block 0.
__global__ void count_deg_kernel(const int* __restrict__ src, const int* __restrict__ dst,
                                 int* deg_out, int* deg_in, int e) {
    int i = blockIdx.x * blockDim.x + threadIdx.x;
    int e4 = e >> 2;
    if (i < e4) {
        int4 s = __ldg((const int4*)src + i);
        int4 d = __ldg((const int4*)dst + i);
        atomicAdd(&deg_out[s.x], 1); atomicAdd(&deg_out[s.y], 1);
        atomicAdd(&deg_out[s.z], 1); atomicAdd(&deg_out[s.w], 1);
        atomicAdd(&deg_in[d.x], 1);  atomicAdd(&deg_in[d.y], 1);
        atomicAdd(&deg_in[d.z], 1);  atomicAdd(&deg_in[d.w], 1);
    }
    if (blockIdx.x == 0 && threadIdx.x < (e & 3)) {
        int t = e4 * 4 + threadIdx.x;
        atomicAdd(&deg_out[src[t]], 1);
        atomicAdd(&deg_in[dst[t]], 1);
    }
}

// ---------------- parallel exclusive scan (3 phases) + rs finalize ----------------
__global__ void scan_block_kernel(const int* __restrict__ deg_in, const int* __restrict__ deg_out,
                                  int* __restrict__ excl, int* __restrict__ blocksums,
                                  float* __restrict__ rs_out, float* __restrict__ rs_in, int n) {
    int i = blockIdx.x * 1024 + threadIdx.x;
    int v = (i < n) ? deg_in[i] : 0;
    if (i < n) {
        rs_in[i]  = rsqrtf((float)max(v, 1));
        rs_out[i] = rsqrtf((float)max(deg_out[i], 1));
    }
    int lane = threadIdx.x & 31, w = threadIdx.x >> 5;
    int x = v;
    #pragma unroll
    for (int o = 1; o < 32; o <<= 1) {
        int y = __shfl_up_sync(0xffffffffu, x, o);
        if (lane >= o) x += y;
    }
    __shared__ int wt[32];
    if (lane == 31) wt[w] = x;
    __syncthreads();
    if (w == 0) {
        int t = wt[lane];
        #pragma unroll
        for (int o = 1; o < 32; o <<= 1) {
            int y = __shfl_up_sync(0xffffffffu, t, o);
            if (lane >= o) t += y;
        }
        wt[lane] = t;
    }
    __syncthreads();
    int base = (w > 0) ? wt[w - 1] : 0;
    int incl = base + x;
    if (i < n) excl[i] = incl - v;
    if (threadIdx.x == 1023) blocksums[blockIdx.x] = incl;
}

__global__ void scan_sums_kernel(int* bs, int nb) {
    int tid = threadIdx.x;              // 64 threads, nb <= 64
    int v = (tid < nb) ? bs[tid] : 0;
    int lane = tid & 31, w = tid >> 5;
    int x = v;
    #pragma unroll
    for (int o = 1; o < 32; o <<= 1) {
        int y = __shfl_up_sync(0xffffffffu, x, o);
        if (lane >= o) x += y;
    }
    __shared__ int wt[2];
    if (lane == 31) wt[w] = x;
    __syncthreads();
    int base = (w == 1) ? wt[0] : 0;
    int incl = base + x;
    if (tid < nb) bs[tid] = incl - v;   // exclusive
}

__global__ void scan_add_kernel(int* __restrict__ offsets, const int* __restrict__ bs,
                                int* __restrict__ cursor, int n, int e) {
    int i = blockIdx.x * 1024 + threadIdx.x;
    if (i < n) {
        int o = offsets[i] + bs[blockIdx.x];
        offsets[i] = o;
        cursor[i] = o;
    }
    if (blockIdx.x == 0 && threadIdx.x == 0) offsets[n] = e;
}

// 4 edges per thread via int4; tail handled by block 0.
__global__ void csr_fill_kernel(const int* __restrict__ src, const int* __restrict__ dst,
                                int* cursor, int* __restrict__ csr_src, int e) {
    int i = blockIdx.x * blockDim.x + threadIdx.x;
    int e4 = e >> 2;
    if (i < e4) {
        int4 s = __ldg((const int4*)src + i);
        int4 d = __ldg((const int4*)dst + i);
        int p0 = atomicAdd(&cursor[d.x], 1);
        int p1 = atomicAdd(&cursor[d.y], 1);
        int p2 = atomicAdd(&cursor[d.z], 1);
        int p3 = atomicAdd(&cursor[d.w], 1);
        csr_src[p0] = s.x; csr_src[p1] = s.y;
        csr_src[p2] = s.z; csr_src[p3] = s.w;
    }
    if (blockIdx.x == 0 && threadIdx.x < (e & 3)) {
        int t = e4 * 4 + threadIdx.x;
        int pos = atomicAdd(&cursor[dst[t]], 1);
        csr_src[pos] = src[t];
    }
}

// ---------------- fused tensor-core GEMM (wmma fp16 in, fp32 acc) ----------------
// Y[r,:] = pre(X[r,:]) @ W  (+ post_bias)
// PRE==1: x * rs_a[r]
// PRE==2: relu(x * rs_a[r] + pre_bias[c]) * rs_b[r]
// PRE==3: x * rs_a[r] + pre_bias[c]
template <int N_OUT, int PRE, int HALF_OUT>
__global__ void gemm_tc_kernel(const float* __restrict__ X, const float* __restrict__ W,
                               void* __restrict__ Yv, int n_rows,
                               const float* __restrict__ rs_a,
                               const float* __restrict__ rs_b,
                               const float* __restrict__ pre_bias,
                               const float* __restrict__ post_bias) {
    constexpr int K = 128;
    constexpr int TILE_M = 64;
    constexpr int LDW = N_OUT + 8;       // halves
    constexpr int LDX = K + 8;           // halves
    constexpr int LDY = N_OUT + 4;       // floats
    constexpr int NF = (N_OUT / 2) / 16; // acc frags per warp (4 or 2)

    extern __shared__ char smem_raw[];
    __half* Ws = (__half*)smem_raw;                       // K x LDW
    __half* Xs = (__half*)(smem_raw + K * LDW * 2);       // TILE_M x LDX
    float*  Ys = (float*)smem_raw;                        // TILE_M x LDY (reused)

    int tid = threadIdx.x;
    int row0 = blockIdx.x * TILE_M;
    int rows = min(TILE_M, n_rows - row0);

    // --- load W (K x N_OUT fp32 row-major) -> fp16 smem ---
    const float4* W4 = (const float4*)W;
    for (int i = tid; i < K * (N_OUT / 4); i += 256) {
        int k = i / (N_OUT / 4);
        int c = (i % (N_OUT / 4)) * 4;
        float4 v = W4[i];
        __half2 p0 = __floats2half2_rn(v.x, v.y);
        __half2 p1 = __floats2half2_rn(v.z, v.w);
        uint2 st; st.x = *(unsigned int*)&p0; st.y = *(unsigned int*)&p1;
        *(uint2*)(Ws + k * LDW + c) = st;
    }

    // --- zero pad rows of Xs (last block) ---
    if (rows < TILE_M) {
        int n_half = (TILE_M - rows) * LDX;
        __half* base = Xs + rows * LDX;
        for (int i = tid; i < n_half; i += 256) base[i] = __ushort_as_half(0);
    }

    // --- load X tile with fused pre-op -> fp16 smem ---
    const float4* X4 = (const float4*)(X + (size_t)row0 * K);
    for (int i = tid; i < rows * (K / 4); i += 256) {
        float4 v = X4[i];
        int r = i / (K / 4);
        int c = (i % (K / 4)) * 4;
        float sa = rs_a[row0 + r];
        if (PRE == 1) {
            v.x *= sa; v.y *= sa; v.z *= sa; v.w *= sa;
        } else {
            v.x = v.x * sa + pre_bias[c + 0];
            v.y = v.y * sa + pre_bias[c + 1];
            v.z = v.z * sa + pre_bias[c + 2];
            v.w = v.w * sa + pre_bias[c + 3];
            if (PRE == 2) {
                float sb = rs_b[row0 + r];
                v.x = fmaxf(v.x, 0.f) * sb;
                v.y = fmaxf(v.y, 0.f) * sb;
                v.z = fmaxf(v.z, 0.f) * sb;
                v.w = fmaxf(v.w, 0.f) * sb;
            }
        }
        __half2 p0 = __floats2half2_rn(v.x, v.y);
        __half2 p1 = __floats2half2_rn(v.z, v.w);
        uint2 st; st.x = *(unsigned int*)&p0; st.y = *(unsigned int*)&p1;
        *(uint2*)(Xs + r * LDX + c) = st;
    }
    __syncthreads();

    // --- compute: 8 warps, warp tile = 16 x (N_OUT/2) ---
    int warp = tid >> 5;
    int warp_m = warp >> 1;              // 0..3
    int warp_n = warp & 1;               // 0..1

    wmma::fragment<wmma::accumulator, 16, 16, 16, float> acc[NF];
    #pragma unroll
    for (int j = 0; j < NF; j++) wmma::fill_fragment(acc[j], 0.0f);

    wmma::fragment<wmma::matrix_a, 16, 16, 16, __half, wmma::row_major> a_frag;
    wmma::fragment<wmma::matrix_b, 16, 16, 16, __half, wmma::row_major> b_frag;

    #pragma unroll
    for (int k = 0; k < K / 16; k++) {
        wmma::load_matrix_sync(a_frag, Xs + (warp_m * 16) * LDX + k * 16, LDX);
        #pragma unroll
        for (int j = 0; j < NF; j++) {
            wmma::load_matrix_sync(b_frag, Ws + (k * 16) * LDW + warp_n * (N_OUT / 2) + j * 16, LDW);
            wmma::mma_sync(acc[j], a_frag, b_frag, acc[j]);
        }
    }
    __syncthreads();   // all smem reads done before Ys overwrites Ws/Xs

    #pragma unroll
    for (int j = 0; j < NF; j++) {
        wmma::store_matrix_sync(Ys + (warp_m * 16) * LDY + warp_n * (N_OUT / 2) + j * 16,
                                acc[j], LDY, wmma::mem_row_major);
    }
    __syncthreads();

    // --- epilogue: bias + convert + store ---
    for (int i = tid; i < rows * (N_OUT / 4); i += 256) {
        int r = i / (N_OUT / 4);
        int c = (i % (N_OUT / 4)) * 4;
        float4 o = *(float4*)(Ys + r * LDY + c);
        if (post_bias) {
            o.x += post_bias[c + 0];
            o.y += post_bias[c + 1];
            o.z += post_bias[c + 2];
            o.w += post_bias[c + 3];
        }
        if (HALF_OUT) {
            __half* Yh = (__half*)Yv;
            __half2 p0 = __floats2half2_rn(o.x, o.y);
            __half2 p1 = __floats2half2_rn(o.z, o.w);
            uint2 st; st.x = *(unsigned int*)&p0; st.y = *(unsigned int*)&p1;
            *(uint2*)(Yh + (size_t)(row0 + r) * N_OUT + c) = st;
        } else {
            *(float4*)((float*)Yv + (size_t)(row0 + r) * N_OUT + c) = o;
        }
    }
}

// ---------------- CSR gather-aggregate (warp per node, 50K independent warps) ----------------
__device__ __forceinline__ void acc_h(float4& a, uint2 v) {
    __half2 h0 = *(__half2*)&v.x;
    __half2 h1 = *(__half2*)&v.y;
    float2 f0 = __half22float2(h0);
    float2 f1 = __half22float2(h1);
    a.x += f0.x; a.y += f0.y; a.z += f1.x; a.w += f1.y;
}

__global__ void gather_kernel(const __half* __restrict__ feat, float* __restrict__ out,
                              const int* __restrict__ offsets, const int* __restrict__ csr_src,
                              int n) {
    int warp = (blockIdx.x * blockDim.x + threadIdx.x) >> 5;
    if (warp >= n) return;
    int lane = threadIdx.x & 31;
    int beg = offsets[warp];
    int end = offsets[warp + 1];

    const uint2* base = (const uint2*)feat;

    float4 a0 = make_float4(0.f, 0.f, 0.f, 0.f);
    float4 a1 = make_float4(0.f, 0.f, 0.f, 0.f);
    float4 a2 = make_float4(0.f, 0.f, 0.f, 0.f);
    float4 a3 = make_float4(0.f, 0.f, 0.f, 0.f);

    int k = beg;
    for (; k + 4 <= end; k += 4) {
        int s0 = __ldg(csr_src + k + 0);
        int s1 = __ldg(csr_src + k + 1);
        int s2 = __ldg(csr_src + k + 2);
        int s3 = __ldg(csr_src + k + 3);
        uint2 v0 = __ldg(base + (size_t)s0 * 32 + lane);
        uint2 v1 = __ldg(base + (size_t)s1 * 32 + lane);
        uint2 v2 = __ldg(base + (size_t)s2 * 32 + lane);
        uint2 v3 = __ldg(base + (size_t)s3 * 32 + lane);
        acc_h(a0, v0);
        acc_h(a1, v1);
        acc_h(a2, v2);
        acc_h(a3, v3);
    }
    for (; k < end; k++) {
        int s = __ldg(csr_src + k);
        uint2 v = __ldg(base + (size_t)s * 32 + lane);
        acc_h(a0, v);
    }
    a0.x += a1.x + a2.x + a3.x;
    a0.y += a1.y + a2.y + a3.y;
    a0.z += a1.z + a2.z + a3.z;
    a0.w += a1.w + a2.w + a3.w;

    *(float4*)(out + (size_t)warp * FEAT + lane * 4) = a0;
}

// ---------------- launch ----------------
extern "C" void kernel_launch(void* const* d_in, const int* in_sizes, int n_in,
                              void* d_out, int out_size) {
    const float* in_feat = (const float*)d_in[0];
    const int*   src     = (const int*)d_in[1];
    const int*   dst     = (const int*)d_in[2];
    const float* W1      = (const float*)d_in[3];
    const float* b1      = (const float*)d_in[4];
    const float* W2      = (const float*)d_in[5];
    const float* b2      = (const float*)d_in[6];
    const float* Wf      = (const float*)d_in[7];
    const float* bf      = (const float*)d_in[8];
    float* out = (float*)d_out;

    int n = in_sizes[0] / FEAT;   // 50000
    int e = in_sizes[1];          // 1600000

    float *buf0, *rs_out, *rs_in;
    __half* h16;
    int *dgo, *dgi, *offs, *curs, *csrc, *bsum;
    cudaGetSymbolAddress((void**)&buf0, g_buf0);
    cudaGetSymbolAddress((void**)&h16, g_h16);
    cudaGetSymbolAddress((void**)&rs_out, g_rs_out);
    cudaGetSymbolAddress((void**)&rs_in, g_rs_in);
    cudaGetSymbolAddress((void**)&dgo, g_deg_out);
    cudaGetSymbolAddress((void**)&dgi, g_deg_in);
    cudaGetSymbolAddress((void**)&offs, g_offsets);
    cudaGetSymbolAddress((void**)&curs, g_cursor);
    cudaGetSymbolAddress((void**)&csrc, g_csr_src);
    cudaGetSymbolAddress((void**)&bsum, g_blocksums);

    const int SMEM_128 = 128 * 136 * 2 + 64 * 136 * 2;   // 52224
    const int SMEM_64  = 128 * 72 * 2 + 64 * 136 * 2;    // 35840
    cudaFuncSetAttribute(gemm_tc_kernel<128, 1, 1>, cudaFuncAttributeMaxDynamicSharedMemorySize, SMEM_128);
    cudaFuncSetAttribute(gemm_tc_kernel<128, 2, 1>, cudaFuncAttributeMaxDynamicSharedMemorySize, SMEM_128);
    cudaFuncSetAttribute(gemm_tc_kernel<64, 3, 0>,  cudaFuncAttributeMaxDynamicSharedMemorySize, SMEM_64);

    // degrees + CSR build (graph identical for both layers; build once)
    init_deg_kernel<<<(n + 255) / 256, 256>>>(dgo, dgi, n);
    int e4 = e >> 2;
    count_deg_kernel<<<(e4 + 255) / 256, 256>>>(src, dst, dgo, dgi, e);

    int nscan_blocks = (n + 1023) / 1024;   // 49
    scan_block_kernel<<<nscan_blocks, 1024>>>(dgi, dgo, offs, bsum, rs_out, rs_in, n);
    scan_sums_kernel<<<1, 64>>>(bsum, nscan_blocks);
    scan_add_kernel<<<nscan_blocks, 1024>>>(offs, bsum, curs, n, e);
    csr_fill_kernel<<<(e4 + 255) / 256, 256>>>(src, dst, curs, csrc, e);

    int gemm_blocks = (n + 63) / 64;
    int gather_blocks = (n * 32 + 255) / 256;

    // layer 1: h16 = (x * rs_out) @ W1
    gemm_tc_kernel<128, 1, 1><<<gemm_blocks, 256, SMEM_128>>>(in_feat, W1, h16, n, rs_out, nullptr, nullptr, nullptr);
    gather_kernel<<<gather_blocks, 256>>>(h16, buf0, offs, csrc, n);

    // layer 2: h16 = (relu(buf0 * rs_in + b1) * rs_out) @ W2
    gemm_tc_kernel<128, 2, 1><<<gemm_blocks, 256, SMEM_128>>>(buf0, W2, h16, n, rs_in, rs_out, b1, nullptr);
    gather_kernel<<<gather_blocks, 256>>>(h16, buf0, offs, csrc, n);

    // final: out = (buf0 * rs_in + b2) @ Wf + bf
    gemm_tc_kernel<64, 3, 0><<<gemm_blocks, 256, SMEM_64>>>(buf0, Wf, out, n, rs_in, nullptr, b2, bf);
}